// round 17
// baseline (speedup 1.0000x reference)
#include <cuda_runtime.h>
#include <cuda_fp16.h>
#include <cstdint>

#define N_NODES 50000
#define N_EDGES 800000
#define D 128
#define N_GRAPHS 128
#define LN_EPS 1e-5f

// ==================== device scratch ====================
__device__ uint2 g_t2[N_NODES * 32];     // dinv-scaled messages, fp16 (256B/node)
__device__ uint2 g_hx[N_NODES * 32];     // node state, fp16 copy (GEMM input)
__device__ float g_h[N_NODES * D];       // node state (fp32, residual/pool truth)
__device__ int   g_cnt[N_NODES];
__device__ float g_dinv[N_NODES];
__device__ int   g_rowoff[N_NODES + 1];
__device__ int   g_rank[N_EDGES];
__device__ int   g_srcs[N_EDGES];

__device__ __forceinline__ uint32_t pack_h2(float a, float b) {
    __half2 h = __floats2half2_rn(a, b);
    return *reinterpret_cast<uint32_t*>(&h);
}

__device__ __forceinline__ __half2 u2h(uint32_t u) {
    return *reinterpret_cast<__half2*>(&u);
}

__device__ __forceinline__ uint32_t s2u(const void* p) {
    return (uint32_t)__cvta_generic_to_shared(p);
}

__device__ __forceinline__ void add_u4(float* acc, uint4 v) {
    float2 q0 = __half22float2(u2h(v.x)), q1 = __half22float2(u2h(v.y));
    float2 q2 = __half22float2(u2h(v.z)), q3 = __half22float2(u2h(v.w));
    acc[0] += q0.x; acc[1] += q0.y;
    acc[2] += q1.x; acc[3] += q1.y;
    acc[4] += q2.x; acc[5] += q2.y;
    acc[6] += q3.x; acc[7] += q3.y;
}

// ==================== CSR build (+ x -> fp16 conversion fused) ====================
// grid covers max(N_EDGES, N_NODES*D/4) thread-slots.
__global__ void count_cvt_kernel(const int* __restrict__ edge_index,
                                 const float* __restrict__ x) {
    int t = blockIdx.x * blockDim.x + threadIdx.x;
    if (t < N_EDGES) {
        int d = edge_index[N_EDGES + t];
        g_rank[t] = atomicAdd(&g_cnt[d], 1);
    }
    if (t < N_NODES * 32) {                 // one float4 -> one uint2 (4 halves)
        float4 v = ((const float4*)x)[t];
        g_hx[t] = make_uint2(pack_h2(v.x, v.y), pack_h2(v.z, v.w));
    }
}

__global__ void scan_kernel() {
    __shared__ int psum[1024];
    int t = threadIdx.x;
    const int CH = (N_NODES + 1023) / 1024;
    int base = t * CH, s = 0;
    for (int i = 0; i < CH; i++) {
        int idx = base + i;
        if (idx < N_NODES) s += g_cnt[idx];
    }
    psum[t] = s;
    __syncthreads();
    for (int o = 1; o < 1024; o <<= 1) {
        int v = 0;
        if (t >= o) v = psum[t - o];
        __syncthreads();
        psum[t] += v;
        __syncthreads();
    }
    int run = (t == 0) ? 0 : psum[t - 1];
    for (int i = 0; i < CH; i++) {
        int idx = base + i;
        if (idx < N_NODES) {
            int c = g_cnt[idx];
            g_rowoff[idx] = run;
            run += c;
            g_dinv[idx] = rsqrtf((float)(c + 1));
        }
    }
    if (t == 1023) g_rowoff[N_NODES] = psum[1023];
}

__global__ void fill_kernel(const int* __restrict__ edge_index) {
    int e = blockIdx.x * blockDim.x + threadIdx.x;
    if (e < N_EDGES) {
        int s = edge_index[e];
        int d = edge_index[N_EDGES + e];
        g_srcs[g_rowoff[d] + g_rank[e]] = s;
    }
}

// ==================== fp16 GEMM (m16n8k16 + ldmatrix + cp.async A) ====================
// C[128x128] per CTA. A is fp16 in gmem (g_hx): cp.async straight to smem,
// 4 double-buffered K-chunks. W staged [k][n] fp16 once. Epilogue scales row r
// by g_dinv[r] before the fp16 message pack.
#define AST 40      // A row stride in halves (80B, 16B-aligned segs, conflict-free)
#define WSTH 136    // W row stride in halves (272B): conflict-free trans LDSM
#define ABUFH (128 * AST)
#define GEMM_SMEM ((128 * WSTH + 2 * ABUFH) * 2)  // 55296 B

__global__ void __launch_bounds__(256, 2) gemm_mma_kernel(const __half* __restrict__ A,
                                                          const float* __restrict__ W) {
    extern __shared__ __half smh[];
    __half* Ws = smh;                  // [128][WSTH]
    __half* Ac = smh + 128 * WSTH;     // 2 x [128][AST]
    int tid = threadIdx.x;
    int r0 = blockIdx.x * 128;

    // cp.async one K-chunk (128 rows x 32 halves = 64B/row) into buffer b
    auto prefetch = [&](int c, int b) {
#pragma unroll
        for (int i = 0; i < 2; i++) {
            int idx = tid + i * 256;        // 512 x 16B segments
            int row = idx >> 2, seg = idx & 3;
            int gr = r0 + row;
            const __half* src = A + (size_t)(gr < N_NODES ? gr : N_NODES - 1) * 128 + c * 32 + seg * 8;
            uint32_t dst = s2u(Ac + b * ABUFH + row * AST + seg * 8);
            int sz = (gr < N_NODES) ? 16 : 0;
            asm volatile("cp.async.cg.shared.global [%0], [%1], 16, %2;"
                         :: "r"(dst), "l"(src), "r"(sz) : "memory");
        }
        asm volatile("cp.async.commit_group;" ::: "memory");
    };

    prefetch(0, 0);

    // stage W [k][n] fp16 while chunk 0 is in flight
    {
        const float4* W4 = (const float4*)W;
#pragma unroll
        for (int i = 0; i < 16; i++) {
            int idx = tid + i * 256;
            int k = idx >> 5, n4 = idx & 31;
            float4 v = W4[idx];
            uint2 p = make_uint2(pack_h2(v.x, v.y), pack_h2(v.z, v.w));
            *(uint2*)&Ws[k * WSTH + n4 * 4] = p;
        }
    }

    int lane = tid & 31, wid = tid >> 5;
    int wm = (wid & 1) * 64;
    int wn = (wid >> 1) * 32;
    int gq = lane >> 2, tq = lane & 3;
    int lrow = lane & 15;
    int lcolA = (lane >> 4) * 8;

    float acc[4][4][4];
#pragma unroll
    for (int mf = 0; mf < 4; mf++)
#pragma unroll
        for (int nf = 0; nf < 4; nf++)
#pragma unroll
            for (int j = 0; j < 4; j++) acc[mf][nf][j] = 0.f;

#pragma unroll
    for (int c = 0; c < 4; c++) {
        if (c < 3) prefetch(c + 1, (c + 1) & 1);
        if (c < 3) asm volatile("cp.async.wait_group 1;" ::: "memory");
        else       asm volatile("cp.async.wait_group 0;" ::: "memory");
        __syncthreads();

        const __half* Ab = Ac + (c & 1) * ABUFH;
#pragma unroll
        for (int ks = 0; ks < 2; ks++) {
            int kb = ks * 16;
            uint32_t a[4][4];
#pragma unroll
            for (int mf = 0; mf < 4; mf++) {
                uint32_t ad = s2u(Ab + (wm + mf * 16 + lrow) * AST + kb + lcolA);
                asm volatile("ldmatrix.sync.aligned.m8n8.x4.shared.b16 {%0,%1,%2,%3}, [%4];"
                             : "=r"(a[mf][0]), "=r"(a[mf][1]), "=r"(a[mf][2]), "=r"(a[mf][3])
                             : "r"(ad));
            }
            uint32_t b[4][2];
#pragma unroll
            for (int nf = 0; nf < 4; nf++) {
                uint32_t ad = s2u(Ws + (c * 32 + kb + lrow) * WSTH + wn + nf * 8);
                asm volatile("ldmatrix.sync.aligned.m8n8.x2.trans.shared.b16 {%0,%1}, [%2];"
                             : "=r"(b[nf][0]), "=r"(b[nf][1]) : "r"(ad));
            }
#pragma unroll
            for (int mf = 0; mf < 4; mf++)
#pragma unroll
                for (int nf = 0; nf < 4; nf++) {
                    asm volatile(
                        "mma.sync.aligned.m16n8k16.row.col.f32.f16.f16.f32 "
                        "{%0,%1,%2,%3}, {%4,%5,%6,%7}, {%8,%9}, {%0,%1,%2,%3};"
                        : "+f"(acc[mf][nf][0]), "+f"(acc[mf][nf][1]),
                          "+f"(acc[mf][nf][2]), "+f"(acc[mf][nf][3])
                        : "r"(a[mf][0]), "r"(a[mf][1]), "r"(a[mf][2]), "r"(a[mf][3]),
                          "r"(b[nf][0]), "r"(b[nf][1]));
                }
        }
        if (c < 3) __syncthreads();
    }

    uint32_t* T = (uint32_t*)g_t2;
#pragma unroll
    for (int mf = 0; mf < 4; mf++) {
        int row0 = r0 + wm + mf * 16 + gq;
        float d0 = (row0 < N_NODES) ? g_dinv[row0] : 0.f;
        float d1 = (row0 + 8 < N_NODES) ? g_dinv[row0 + 8] : 0.f;
#pragma unroll
        for (int nf = 0; nf < 4; nf++) {
            int c2 = (wn + nf * 8 + 2 * tq) >> 1;
            if (row0 < N_NODES)
                T[row0 * 64 + c2] = pack_h2(acc[mf][nf][0] * d0, acc[mf][nf][1] * d0);
            if (row0 + 8 < N_NODES)
                T[(row0 + 8) * 64 + c2] = pack_h2(acc[mf][nf][2] * d1, acc[mf][nf][3] * d1);
        }
    }
}

// ==================== aggregation: HALF-WARP per node, weight-free ====================
// also writes the fp16 node-state copy (g_hx) consumed by the next GEMM.
__global__ void __launch_bounds__(256) agg_kernel(const float* __restrict__ bias,
                                                  const float* __restrict__ gamma,
                                                  const float* __restrict__ beta,
                                                  int mode) {
    int t = blockIdx.x * blockDim.x + threadIdx.x;
    int n = t >> 4;
    int hl = threadIdx.x & 15;
    if (n >= N_NODES) return;

    const uint4* T4 = (const uint4*)g_t2;

    float acc[8];
#pragma unroll
    for (int j = 0; j < 8; j++) acc[j] = 0.f;
    add_u4(acc, T4[n * 16 + hl]);               // self loop

    int e0 = g_rowoff[n], e1 = g_rowoff[n + 1];
    int e = e0;
    for (int r = (e1 - e0) & 3; r > 0; r--, e++)
        add_u4(acc, T4[(size_t)g_srcs[e] * 16 + hl]);
    for (; e < e1; e += 4) {
        int s0 = g_srcs[e], s1 = g_srcs[e + 1], s2 = g_srcs[e + 2], s3 = g_srcs[e + 3];
        uint4 v0 = T4[(size_t)s0 * 16 + hl];
        uint4 v1 = T4[(size_t)s1 * 16 + hl];
        uint4 v2 = T4[(size_t)s2 * 16 + hl];
        uint4 v3 = T4[(size_t)s3 * 16 + hl];
        __half2 sx = __hadd2(__hadd2(u2h(v0.x), u2h(v1.x)), __hadd2(u2h(v2.x), u2h(v3.x)));
        __half2 sy = __hadd2(__hadd2(u2h(v0.y), u2h(v1.y)), __hadd2(u2h(v2.y), u2h(v3.y)));
        __half2 sz = __hadd2(__hadd2(u2h(v0.z), u2h(v1.z)), __hadd2(u2h(v2.z), u2h(v3.z)));
        __half2 sw = __hadd2(__hadd2(u2h(v0.w), u2h(v1.w)), __hadd2(u2h(v2.w), u2h(v3.w)));
        float2 f0 = __half22float2(sx), f1 = __half22float2(sy);
        float2 f2 = __half22float2(sz), f3 = __half22float2(sw);
        acc[0] += f0.x; acc[1] += f0.y;
        acc[2] += f1.x; acc[3] += f1.y;
        acc[4] += f2.x; acc[5] += f2.y;
        acc[6] += f3.x; acc[7] += f3.y;
    }

    float dn = g_dinv[n];
    {
        float4 b0 = ((const float4*)bias)[hl * 2];
        float4 b1 = ((const float4*)bias)[hl * 2 + 1];
        acc[0] = acc[0] * dn + b0.x; acc[1] = acc[1] * dn + b0.y;
        acc[2] = acc[2] * dn + b0.z; acc[3] = acc[3] * dn + b0.w;
        acc[4] = acc[4] * dn + b1.x; acc[5] = acc[5] * dn + b1.y;
        acc[6] = acc[6] * dn + b1.z; acc[7] = acc[7] * dn + b1.w;
    }

    float4* H4 = (float4*)g_h;
    uint4* HX = (uint4*)g_hx;
    if (mode == 0) {
        H4[n * 32 + hl * 2]     = make_float4(acc[0], acc[1], acc[2], acc[3]);
        H4[n * 32 + hl * 2 + 1] = make_float4(acc[4], acc[5], acc[6], acc[7]);
        HX[n * 16 + hl] = make_uint4(pack_h2(acc[0], acc[1]), pack_h2(acc[2], acc[3]),
                                     pack_h2(acc[4], acc[5]), pack_h2(acc[6], acc[7]));
    } else {
        float s1 = 0.f, s2 = 0.f;
#pragma unroll
        for (int j = 0; j < 8; j++) { s1 += acc[j]; s2 += acc[j] * acc[j]; }
#pragma unroll
        for (int o = 8; o > 0; o >>= 1) {
            s1 += __shfl_xor_sync(0xffffffffu, s1, o);
            s2 += __shfl_xor_sync(0xffffffffu, s2, o);
        }
        float mu = s1 * (1.f / 128.f);
        float var = s2 * (1.f / 128.f) - mu * mu;
        float rs = rsqrtf(var + LN_EPS);
        float4 g0 = ((const float4*)gamma)[hl * 2];
        float4 g1 = ((const float4*)gamma)[hl * 2 + 1];
        float4 be0 = ((const float4*)beta)[hl * 2];
        float4 be1 = ((const float4*)beta)[hl * 2 + 1];
        float4 h0 = H4[n * 32 + hl * 2];
        float4 h1 = H4[n * 32 + hl * 2 + 1];
        h0.x += fmaxf((acc[0] - mu) * rs * g0.x + be0.x, 0.f);
        h0.y += fmaxf((acc[1] - mu) * rs * g0.y + be0.y, 0.f);
        h0.z += fmaxf((acc[2] - mu) * rs * g0.z + be0.z, 0.f);
        h0.w += fmaxf((acc[3] - mu) * rs * g0.w + be0.w, 0.f);
        h1.x += fmaxf((acc[4] - mu) * rs * g1.x + be1.x, 0.f);
        h1.y += fmaxf((acc[5] - mu) * rs * g1.y + be1.y, 0.f);
        h1.z += fmaxf((acc[6] - mu) * rs * g1.z + be1.z, 0.f);
        h1.w += fmaxf((acc[7] - mu) * rs * g1.w + be1.w, 0.f);
        H4[n * 32 + hl * 2] = h0;
        H4[n * 32 + hl * 2 + 1] = h1;
        HX[n * 16 + hl] = make_uint4(pack_h2(h0.x, h0.y), pack_h2(h0.z, h0.w),
                                     pack_h2(h1.x, h1.y), pack_h2(h1.z, h1.w));
    }
}

// ==================== fused pool + readout ====================
__global__ void __launch_bounds__(128) readout_fused_kernel(
        const int* __restrict__ batch_idx,
        const float* __restrict__ W1, const float* __restrict__ b1,
        const float* __restrict__ W2, const float* __restrict__ b2,
        float* __restrict__ out) {
    __shared__ float yrow[128];
    __shared__ float partial[4];
    int g = blockIdx.x, j = threadIdx.x;

    int lo = 0, hi = N_NODES;
    while (lo < hi) { int m = (lo + hi) >> 1; if (batch_idx[m] < g) lo = m + 1; else hi = m; }
    int start = lo;
    lo = start; hi = N_NODES;
    while (lo < hi) { int m = (lo + hi) >> 1; if (batch_idx[m] < g + 1) lo = m + 1; else hi = m; }
    int end = lo;

    float acc = 0.f;
    int n = start;
    for (; n + 8 <= end; n += 8) {
        acc += g_h[(size_t)(n + 0) * D + j] + g_h[(size_t)(n + 1) * D + j]
             + g_h[(size_t)(n + 2) * D + j] + g_h[(size_t)(n + 3) * D + j]
             + g_h[(size_t)(n + 4) * D + j] + g_h[(size_t)(n + 5) * D + j]
             + g_h[(size_t)(n + 6) * D + j] + g_h[(size_t)(n + 7) * D + j];
    }
    for (; n < end; n++) acc += g_h[(size_t)n * D + j];
    yrow[j] = acc;
    __syncthreads();

    float m1 = 0.f;
#pragma unroll 8
    for (int k = 0; k < 128; k++) m1 += yrow[k] * W1[k * D + j];
    float z = fmaxf(m1 + b1[j], 0.f);
    float p = z * W2[j];
#pragma unroll
    for (int o = 16; o > 0; o >>= 1) p += __shfl_xor_sync(0xffffffffu, p, o);
    if ((j & 31) == 0) partial[j >> 5] = p;
    __syncthreads();
    if (j == 0) out[g] = partial[0] + partial[1] + partial[2] + partial[3] + b2[0];
}

// ==================== launch ====================
extern "C" void kernel_launch(void* const* d_in, const int* in_sizes, int n_in,
                              void* d_out, int out_size) {
    const float* x      = (const float*)d_in[0];
    const int*   ei     = (const int*)d_in[1];
    const int*   batch  = (const int*)d_in[2];
    const float* W_enc  = (const float*)d_in[3];
    const float* b_enc  = (const float*)d_in[4];
    const float* W_blk  = (const float*)d_in[5];
    const float* b_blk  = (const float*)d_in[6];
    const float* gamma  = (const float*)d_in[7];
    const float* beta   = (const float*)d_in[8];
    const float* W1     = (const float*)d_in[9];
    const float* b1     = (const float*)d_in[10];
    const float* W2     = (const float*)d_in[11];
    const float* b2     = (const float*)d_in[12];
    float* out = (float*)d_out;

    __half* dhx = nullptr;
    cudaGetSymbolAddress((void**)&dhx, g_hx);
    int* dcnt = nullptr;
    cudaGetSymbolAddress((void**)&dcnt, g_cnt);

    cudaFuncSetAttribute(gemm_mma_kernel, cudaFuncAttributeMaxDynamicSharedMemorySize, GEMM_SMEM);

    const int TB = 256;
    int nblk_cc    = (N_NODES * 32 + TB - 1) / TB;   // covers both count & convert ranges
    int nblk_edges = (N_EDGES + TB - 1) / TB;
    int nblk_gemm  = (N_NODES + 127) / 128;
    int nblk_agg   = (N_NODES * 16 + TB - 1) / TB;

    // Kernel order: count+cvt(1), scan(2), fill(3), gemm(4) -> ncu slot on GEMM v7.
    cudaMemsetAsync(dcnt, 0, N_NODES * sizeof(int));
    count_cvt_kernel<<<nblk_cc, TB>>>(ei, x);
    scan_kernel<<<1, 1024>>>();
    fill_kernel<<<nblk_edges, TB>>>(ei);

    // encoder (reads fp16 x copy)
    gemm_mma_kernel<<<nblk_gemm, TB, GEMM_SMEM>>>(dhx, W_enc);
    agg_kernel<<<nblk_agg, TB>>>(b_enc, nullptr, nullptr, 0);

    // standalone blk0
    gemm_mma_kernel<<<nblk_gemm, TB, GEMM_SMEM>>>(dhx, W_blk + 0 * D * D);
    agg_kernel<<<nblk_agg, TB>>>(b_blk + 0 * D, nullptr, nullptr, 0);

    // res blocks
    for (int l = 0; l < 3; l++) {
        gemm_mma_kernel<<<nblk_gemm, TB, GEMM_SMEM>>>(dhx, W_blk + l * D * D);
        agg_kernel<<<nblk_agg, TB>>>(b_blk + l * D, gamma + l * D, beta + l * D, 1);
    }

    // fused pool + readout
    readout_fused_kernel<<<N_GRAPHS, 128>>>(batch, W1, b1, W2, b2, out);
}